// round 7
// baseline (speedup 1.0000x reference)
#include <cuda_runtime.h>
#include <cstdint>
#include <cstddef>

// Problem constants
#define BSZ 256      // batch
#define TT  512      // time steps
#define EE  256      // input dim
#define HH  256      // hidden dim
#define NB  4        // batches per cluster

// h buffer geometry: [2][NB][2 halves][HPITCH]; pad 132 so the two K-half
// streams land on different banks (528B offset -> +4 banks).
#define HPITCH 132
#define BST    (2 * HPITCH)          // batch stride (floats)
#define PST    (NB * BST)            // ping-pong buffer stride (floats)

typedef unsigned long long ull;

// ---- packed f32x2 helpers (Blackwell) -------------------------------------
__device__ __forceinline__ ull fma2(ull a, ull b, ull c) {
    ull d;
    asm("fma.rn.f32x2 %0, %1, %2, %3;" : "=l"(d) : "l"(a), "l"(b), "l"(c));
    return d;
}
__device__ __forceinline__ ull splat2(float x) {
    ull d;
    asm("mov.b64 %0, {%1, %1};" : "=l"(d) : "f"(x));
    return d;
}
__device__ __forceinline__ float2 unpack2(ull a) {
    float2 r;
    asm("mov.b64 {%0, %1}, %2;" : "=f"(r.x), "=f"(r.y) : "l"(a));
    return r;
}
__device__ __forceinline__ uint32_t smem_u32(const void* p) {
    uint32_t a;
    asm("{ .reg .u64 t; cvta.to.shared.u64 t, %1; cvt.u32.u64 %0, t; }"
        : "=r"(a) : "l"(p));
    return a;
}
// fast tanh via MUFU exp: (e^{2z}-1)/(e^{2z}+1)
__device__ __forceinline__ float ftanh(float z) {
    float e = __expf(2.0f * z);
    return __fdividef(e - 1.0f, e + 1.0f);
}

// ---------------------------------------------------------------------------
// Phase 1: gates = sigmoid(X @ Wx^T + b)  via packed-f32x2 SGEMM. (unchanged)
// ---------------------------------------------------------------------------
__global__ __launch_bounds__(256, 2) void gates_kernel(
    const float* __restrict__ X, const float* __restrict__ W,
    const float* __restrict__ bias, float* __restrict__ G)
{
    __shared__ __align__(16) float As[16][128];
    __shared__ __align__(16) float Ws[16][128];

    const int tid = threadIdx.x;
    const int bm = blockIdx.x * 128;
    const int bn = blockIdx.y * 128;
    const int tx = tid & 15;
    const int ty = tid >> 4;
    const int lr = tid >> 2;
    const int lc = (tid & 3) << 2;

    ull acc[8][4];
#pragma unroll
    for (int i = 0; i < 8; ++i)
#pragma unroll
        for (int jj = 0; jj < 4; ++jj) acc[i][jj] = 0ull;

    const float* Xp0 = X + (size_t)(bm + lr) * EE + lc;
    const float* Xp1 = X + (size_t)(bm + lr + 64) * EE + lc;
    const float* Wp0 = W + (size_t)(bn + lr) * EE + lc;
    const float* Wp1 = W + (size_t)(bn + lr + 64) * EE + lc;

    float4 pa0 = *(const float4*)(Xp0);
    float4 pa1 = *(const float4*)(Xp1);
    float4 pw0 = *(const float4*)(Wp0);
    float4 pw1 = *(const float4*)(Wp1);

#pragma unroll 1
    for (int k0 = 0; k0 < EE; k0 += 16) {
        __syncthreads();
        As[lc + 0][lr] = pa0.x; As[lc + 1][lr] = pa0.y;
        As[lc + 2][lr] = pa0.z; As[lc + 3][lr] = pa0.w;
        As[lc + 0][lr + 64] = pa1.x; As[lc + 1][lr + 64] = pa1.y;
        As[lc + 2][lr + 64] = pa1.z; As[lc + 3][lr + 64] = pa1.w;
        Ws[lc + 0][lr] = pw0.x; Ws[lc + 1][lr] = pw0.y;
        Ws[lc + 2][lr] = pw0.z; Ws[lc + 3][lr] = pw0.w;
        Ws[lc + 0][lr + 64] = pw1.x; Ws[lc + 1][lr + 64] = pw1.y;
        Ws[lc + 2][lr + 64] = pw1.z; Ws[lc + 3][lr + 64] = pw1.w;
        __syncthreads();

        if (k0 + 16 < EE) {
            pa0 = *(const float4*)(Xp0 + k0 + 16);
            pa1 = *(const float4*)(Xp1 + k0 + 16);
            pw0 = *(const float4*)(Wp0 + k0 + 16);
            pw1 = *(const float4*)(Wp1 + k0 + 16);
        }

#pragma unroll
        for (int k = 0; k < 16; ++k) {
            float a[8];
            *(float4*)&a[0] = *(const float4*)&As[k][ty * 8];
            *(float4*)&a[4] = *(const float4*)&As[k][ty * 8 + 4];
            ulonglong2 u0 = *(const ulonglong2*)&Ws[k][tx * 8];
            ulonglong2 u1 = *(const ulonglong2*)&Ws[k][tx * 8 + 4];
            const ull b0 = u0.x, b1 = u0.y, b2 = u1.x, b3 = u1.y;
#pragma unroll
            for (int i = 0; i < 8; ++i) {
                const ull s = splat2(a[i]);
                acc[i][0] = fma2(s, b0, acc[i][0]);
                acc[i][1] = fma2(s, b1, acc[i][1]);
                acc[i][2] = fma2(s, b2, acc[i][2]);
                acc[i][3] = fma2(s, b3, acc[i][3]);
            }
        }
    }

    float bb[8];
#pragma unroll
    for (int jj = 0; jj < 8; ++jj) bb[jj] = bias[bn + tx * 8 + jj];

#pragma unroll
    for (int i = 0; i < 8; ++i) {
        const size_t m = bm + ty * 8 + i;
        float v[8];
#pragma unroll
        for (int jj = 0; jj < 4; ++jj) {
            float2 z = unpack2(acc[i][jj]);
            float z0 = z.x + bb[2 * jj];
            float z1 = z.y + bb[2 * jj + 1];
            v[2 * jj]     = 1.0f / (1.0f + __expf(-z0));
            v[2 * jj + 1] = 1.0f / (1.0f + __expf(-z1));
        }
        float4 o0 = {v[0], v[1], v[2], v[3]};
        float4 o1 = {v[4], v[5], v[6], v[7]};
        *(float4*)(G + m * HH + bn + tx * 8)     = o0;
        *(float4*)(G + m * HH + bn + tx * 8 + 4) = o1;
    }
}

// ---------------------------------------------------------------------------
// Phase 2: MGU recurrence — sync-free step skeleton.
//   Cluster(2) x 64, NB=4 batches, 512 steps. CTA rank r owns rows
//   [r*128, r*128+128). 256 threads: pair layout j = tid>>1, kh = tid&1.
//   Thread holds W[jg][kh*128..+128) in 64 packed regs; 4 batch accumulators.
//   Per step: wait mb[p] (parity, acquire.cluster) -> matvec (32 iters = all
//   128 K elems; R6 bug was 16) -> __shfl_xor(1) pair-reduce -> lane kh
//   updates batches {2kh,2kh+1} (h_prev in registers) -> stores (STG out,
//   STS local, st.cluster peer) -> per-thread arrive.release on LOCAL mb[q]
//   + REMOTE peer mb[q]. mb count = 512 (256 local + 256 peer arrivals) —
//   the mbarrier IS the step barrier; no __syncthreads in the loop.
// ---------------------------------------------------------------------------
__global__ void __cluster_dims__(2, 1, 1) __launch_bounds__(256, 1)
mgu_scan(const float* __restrict__ Whw, const float* __restrict__ Whb,
         float* out)
{
    __shared__ __align__(16) float hsh[2 * PST];   // [p][b][half][HPITCH]
    __shared__ __align__(8)  ull  bars[2];

    const int tid = threadIdx.x;
    const int j   = tid >> 1;       // row within CTA half (0..127)
    const int kh  = tid & 1;        // K half (0..1)
    uint32_t rank;
    asm("mov.u32 %0, %%cluster_ctarank;" : "=r"(rank));
    const int jg = (int)rank * 128 + j;
    const int bbase = (blockIdx.x >> 1) * NB;
    const int b0 = 2 * kh;          // this lane finalizes batches b0, b0+1

    // --- W row half (128 floats) into 64 packed registers ---
    ull wv[64];
    {
        const ulonglong2* wp =
            (const ulonglong2*)(Whw + (size_t)jg * HH + kh * 128);
#pragma unroll
        for (int i = 0; i < 32; ++i) {
            ulonglong2 v = wp[i];
            wv[2 * i] = v.x; wv[2 * i + 1] = v.y;
        }
    }

    for (int i = tid; i < 2 * PST; i += 256) hsh[i] = 0.0f;

    if (tid == 0) {
        asm volatile("mbarrier.init.shared.b64 [%0], 512;"
                     :: "r"(smem_u32(&bars[0])) : "memory");
        asm volatile("mbarrier.init.shared.b64 [%0], 512;"
                     :: "r"(smem_u32(&bars[1])) : "memory");
    }

    const float biasr = Whb[jg];

    // out pointers for the 2 owned (batch,row) streams
    float* po0 = out + (size_t)(bbase + b0) * TT * HH + jg;
    float* po1 = po0 + (size_t)TT * HH;

    float gc0 = po0[0], gc1 = po1[0];   // gates t=0
    float hc0 = 0.0f, hc1 = 0.0f;       // persistent h for owned streams

    // cluster addresses
    const uint32_t hl  = smem_u32(hsh);
    const uint32_t bl0 = smem_u32(&bars[0]);
    uint32_t hr, br0;
    asm("mapa.shared::cluster.u32 %0, %1, %2;"
        : "=r"(hr) : "r"(hl), "r"(rank ^ 1u));
    asm("mapa.shared::cluster.u32 %0, %1, %2;"
        : "=r"(br0) : "r"(bl0), "r"(rank ^ 1u));

    // local/peer h store offsets (floats) within a buffer: [b][half=rank][j]
    const int st_off0 = b0 * BST + (int)rank * HPITCH + j;   // batch b0
    const int st_off1 = st_off0 + BST;                       // batch b0+1

    __syncthreads();
    // one-time: both CTAs' smem + mbarrier init visible cluster-wide
    asm volatile("barrier.cluster.arrive.aligned;" ::: "memory");
    asm volatile("barrier.cluster.wait.aligned;"   ::: "memory");

    uint32_t ph0 = 0, ph1 = 0;

#pragma unroll 1
    for (int t = 0; t < TT; ++t) {
        const int p = t & 1;
        const int q = p ^ 1;
        const bool not_last = (t + 1 < TT);

        // prefetch gates for t+1 (issued before the wait; DRAM hidden by step)
        float gn0 = 0.f, gn1 = 0.f;
        if (not_last) {
            const size_t o = (size_t)(t + 1) * HH;
            gn0 = po0[o]; gn1 = po1[o];
        }

        // step barrier: wait for all 512 arrivals of step t-1 on mb[p]
        if (t > 0) {
            const uint32_t mb = bl0 + (uint32_t)p * 8u;
            const uint32_t par = p ? ph1 : ph0;
            uint32_t done;
            do {
                asm volatile(
                    "{\n\t.reg .pred P;\n\t"
                    "mbarrier.try_wait.parity.acquire.cluster.shared::cta.b64 "
                    "P, [%1], %2, 0x989680;\n\t"
                    "selp.b32 %0, 1, 0, P;\n\t}"
                    : "=r"(done) : "r"(mb), "r"(par) : "memory");
            } while (!done);
            if (p) ph1 ^= 1; else ph0 ^= 1;
        }

        // ---- matvec over this thread's K-half (128 elems = 32 x 4), 4 b ----
        const float* hb = hsh + p * PST + kh * HPITCH;
        const ulonglong2* x0 = (const ulonglong2*)(hb);
        const ulonglong2* x1 = (const ulonglong2*)(hb + BST);
        const ulonglong2* x2 = (const ulonglong2*)(hb + 2 * BST);
        const ulonglong2* x3 = (const ulonglong2*)(hb + 3 * BST);
        ull a0 = 0, a1 = 0, a2 = 0, a3 = 0;
#pragma unroll
        for (int i = 0; i < 32; ++i) {
            const ulonglong2 v0 = x0[i];
            const ulonglong2 v1 = x1[i];
            const ulonglong2 v2 = x2[i];
            const ulonglong2 v3 = x3[i];
            const ull wA = wv[2 * i], wB = wv[2 * i + 1];
            a0 = fma2(wA, v0.x, a0); a1 = fma2(wA, v1.x, a1);
            a2 = fma2(wA, v2.x, a2); a3 = fma2(wA, v3.x, a3);
            a0 = fma2(wB, v0.y, a0); a1 = fma2(wB, v1.y, a1);
            a2 = fma2(wB, v2.y, a2); a3 = fma2(wB, v3.y, a3);
        }
        // pair-sum within lane, then cross-lane pair reduce via shfl.xor(1)
        float2 u;
        u = unpack2(a0); float r0 = u.x + u.y;
        u = unpack2(a1); float r1 = u.x + u.y;
        u = unpack2(a2); float r2 = u.x + u.y;
        u = unpack2(a3); float r3 = u.x + u.y;
        const unsigned FULL = 0xffffffffu;
        const float s0 = r0 + __shfl_xor_sync(FULL, r0, 1);
        const float s1 = r1 + __shfl_xor_sync(FULL, r1, 1);
        const float s2 = r2 + __shfl_xor_sync(FULL, r2, 1);
        const float s3 = r3 + __shfl_xor_sync(FULL, r3, 1);

        // ---- update the 2 owned streams (h_prev in registers) ----
        const float zA = (kh ? s2 : s0) + biasr;
        const float zB = (kh ? s3 : s1) + biasr;
        const float thA = ftanh(zA);
        const float thB = ftanh(zB);
        hc0 = fmaf(gc0, hc0 - thA, thA);    // g*h + (1-g)*tanh
        hc1 = fmaf(gc1, hc1 - thB, thB);
        gc0 = gn0; gc1 = gn1;

        // ---- stores: out (always), local + peer h buffer q ----
        const size_t ot = (size_t)t * HH;
        po0[ot] = hc0;
        po1[ot] = hc1;
        if (not_last) {
            const int base = q * PST;
            hsh[base + st_off0] = hc0;
            hsh[base + st_off1] = hc1;
            const uint32_t ra0 = hr + (uint32_t)(base + st_off0) * 4u;
            const uint32_t ra1 = hr + (uint32_t)(base + st_off1) * 4u;
            asm volatile("st.shared::cluster.f32 [%0], %1;"
                         :: "r"(ra0), "f"(hc0) : "memory");
            asm volatile("st.shared::cluster.f32 [%0], %1;"
                         :: "r"(ra1), "f"(hc1) : "memory");
            // per-thread arrivals: local mb[q] (orders my STS for local
            // acquirers) + peer mb[q] (orders my st.cluster for peer).
            const uint32_t off = (uint32_t)q * 8u;
            asm volatile(
                "mbarrier.arrive.release.cluster.shared::cta.b64 _, [%0];"
                :: "r"(bl0 + off) : "memory");
            asm volatile(
                "mbarrier.arrive.release.cluster.shared::cluster.b64 _, [%0];"
                :: "r"(br0 + off) : "memory");
        }
    }

    // Trailing cluster sync: no CTA exits while peer DSMEM traffic may be
    // in flight toward it.
    asm volatile("barrier.cluster.arrive.aligned;" ::: "memory");
    asm volatile("barrier.cluster.wait.aligned;"   ::: "memory");
}

// ---------------------------------------------------------------------------
extern "C" void kernel_launch(void* const* d_in, const int* in_sizes, int n_in,
                              void* d_out, int out_size)
{
    const float* x   = (const float*)d_in[0];  // [B,T,E]
    const float* Wxw = (const float*)d_in[1];  // [H,E]
    const float* Wxb = (const float*)d_in[2];  // [H]
    const float* Whw = (const float*)d_in[3];  // [H,H]
    const float* Whb = (const float*)d_in[4];  // [H]
    float* out = (float*)d_out;                // [B,T,H]

    dim3 g1(BSZ * TT / 128, HH / 128);
    gates_kernel<<<g1, 256>>>(x, Wxw, Wxb, out);

    mgu_scan<<<(BSZ / NB) * 2, 256>>>(Whw, Whb, out);
}

// round 8
// speedup vs baseline: 1.1483x; 1.1483x over previous
#include <cuda_runtime.h>
#include <cstdint>
#include <cstddef>

// Problem constants
#define BSZ 256      // batch
#define TT  512      // time steps
#define EE  256      // input dim
#define HH  256      // hidden dim
#define NB  4        // batches per cluster

// h buffer geometry: [2][NB][2 halves][HPITCH]; pad 132 so the two K-half
// streams land on different banks (528B offset -> +4 banks).
#define HPITCH 132
#define BST    (2 * HPITCH)          // batch stride (floats)
#define PST    (NB * BST)            // ping-pong buffer stride (floats)

typedef unsigned long long ull;

// ---- packed f32x2 helpers (Blackwell) -------------------------------------
__device__ __forceinline__ ull fma2(ull a, ull b, ull c) {
    ull d;
    asm("fma.rn.f32x2 %0, %1, %2, %3;" : "=l"(d) : "l"(a), "l"(b), "l"(c));
    return d;
}
__device__ __forceinline__ ull splat2(float x) {
    ull d;
    asm("mov.b64 %0, {%1, %1};" : "=l"(d) : "f"(x));
    return d;
}
__device__ __forceinline__ float2 unpack2(ull a) {
    float2 r;
    asm("mov.b64 {%0, %1}, %2;" : "=f"(r.x), "=f"(r.y) : "l"(a));
    return r;
}
__device__ __forceinline__ uint32_t smem_u32(const void* p) {
    uint32_t a;
    asm("{ .reg .u64 t; cvta.to.shared.u64 t, %1; cvt.u32.u64 %0, t; }"
        : "=r"(a) : "l"(p));
    return a;
}
// fast tanh via MUFU exp: (e^{2z}-1)/(e^{2z}+1)
__device__ __forceinline__ float ftanh(float z) {
    float e = __expf(2.0f * z);
    return __fdividef(e - 1.0f, e + 1.0f);
}

// ---------------------------------------------------------------------------
// Phase 1: gates = sigmoid(X @ Wx^T + b)  via packed-f32x2 SGEMM. (unchanged)
// ---------------------------------------------------------------------------
__global__ __launch_bounds__(256, 2) void gates_kernel(
    const float* __restrict__ X, const float* __restrict__ W,
    const float* __restrict__ bias, float* __restrict__ G)
{
    __shared__ __align__(16) float As[16][128];
    __shared__ __align__(16) float Ws[16][128];

    const int tid = threadIdx.x;
    const int bm = blockIdx.x * 128;
    const int bn = blockIdx.y * 128;
    const int tx = tid & 15;
    const int ty = tid >> 4;
    const int lr = tid >> 2;
    const int lc = (tid & 3) << 2;

    ull acc[8][4];
#pragma unroll
    for (int i = 0; i < 8; ++i)
#pragma unroll
        for (int jj = 0; jj < 4; ++jj) acc[i][jj] = 0ull;

    const float* Xp0 = X + (size_t)(bm + lr) * EE + lc;
    const float* Xp1 = X + (size_t)(bm + lr + 64) * EE + lc;
    const float* Wp0 = W + (size_t)(bn + lr) * EE + lc;
    const float* Wp1 = W + (size_t)(bn + lr + 64) * EE + lc;

    float4 pa0 = *(const float4*)(Xp0);
    float4 pa1 = *(const float4*)(Xp1);
    float4 pw0 = *(const float4*)(Wp0);
    float4 pw1 = *(const float4*)(Wp1);

#pragma unroll 1
    for (int k0 = 0; k0 < EE; k0 += 16) {
        __syncthreads();
        As[lc + 0][lr] = pa0.x; As[lc + 1][lr] = pa0.y;
        As[lc + 2][lr] = pa0.z; As[lc + 3][lr] = pa0.w;
        As[lc + 0][lr + 64] = pa1.x; As[lc + 1][lr + 64] = pa1.y;
        As[lc + 2][lr + 64] = pa1.z; As[lc + 3][lr + 64] = pa1.w;
        Ws[lc + 0][lr] = pw0.x; Ws[lc + 1][lr] = pw0.y;
        Ws[lc + 2][lr] = pw0.z; Ws[lc + 3][lr] = pw0.w;
        Ws[lc + 0][lr + 64] = pw1.x; Ws[lc + 1][lr + 64] = pw1.y;
        Ws[lc + 2][lr + 64] = pw1.z; Ws[lc + 3][lr + 64] = pw1.w;
        __syncthreads();

        if (k0 + 16 < EE) {
            pa0 = *(const float4*)(Xp0 + k0 + 16);
            pa1 = *(const float4*)(Xp1 + k0 + 16);
            pw0 = *(const float4*)(Wp0 + k0 + 16);
            pw1 = *(const float4*)(Wp1 + k0 + 16);
        }

#pragma unroll
        for (int k = 0; k < 16; ++k) {
            float a[8];
            *(float4*)&a[0] = *(const float4*)&As[k][ty * 8];
            *(float4*)&a[4] = *(const float4*)&As[k][ty * 8 + 4];
            ulonglong2 u0 = *(const ulonglong2*)&Ws[k][tx * 8];
            ulonglong2 u1 = *(const ulonglong2*)&Ws[k][tx * 8 + 4];
            const ull b0 = u0.x, b1 = u0.y, b2 = u1.x, b3 = u1.y;
#pragma unroll
            for (int i = 0; i < 8; ++i) {
                const ull s = splat2(a[i]);
                acc[i][0] = fma2(s, b0, acc[i][0]);
                acc[i][1] = fma2(s, b1, acc[i][1]);
                acc[i][2] = fma2(s, b2, acc[i][2]);
                acc[i][3] = fma2(s, b3, acc[i][3]);
            }
        }
    }

    float bb[8];
#pragma unroll
    for (int jj = 0; jj < 8; ++jj) bb[jj] = bias[bn + tx * 8 + jj];

#pragma unroll
    for (int i = 0; i < 8; ++i) {
        const size_t m = bm + ty * 8 + i;
        float v[8];
#pragma unroll
        for (int jj = 0; jj < 4; ++jj) {
            float2 z = unpack2(acc[i][jj]);
            float z0 = z.x + bb[2 * jj];
            float z1 = z.y + bb[2 * jj + 1];
            v[2 * jj]     = 1.0f / (1.0f + __expf(-z0));
            v[2 * jj + 1] = 1.0f / (1.0f + __expf(-z1));
        }
        float4 o0 = {v[0], v[1], v[2], v[3]};
        float4 o1 = {v[4], v[5], v[6], v[7]};
        *(float4*)(G + m * HH + bn + tx * 8)     = o0;
        *(float4*)(G + m * HH + bn + tx * 8 + 4) = o1;
    }
}

// ---------------------------------------------------------------------------
// Phase 2: MGU recurrence — mbarrier step skeleton, WARP-AGGREGATED arrives.
//   Cluster(2) x 64, NB=4 batches, 512 steps. CTA rank r owns rows
//   [r*128, r*128+128). 256 threads: pair layout j = tid>>1, kh = tid&1.
//   Thread holds W[jg][kh*128..+128) in 64 packed regs; 4 batch accumulators.
//   Per step: wait mb[p] (parity, acquire.cluster) -> matvec (32 iters) ->
//   __shfl_xor(1) pair-reduce -> lane kh updates batches {2kh,2kh+1}
//   (h_prev in registers) -> stores (STG out, STS local, st.cluster peer) ->
//   __syncwarp -> WARP LANE 0 ONLY arrives on local mb[q] + peer mb[q].
//   mb count = 16 (8 local warps + 8 peer warps). R7's mistake was 512
//   per-thread arrives (same-address RMWs serialize); 16 is ~2-4 cyc each.
//   Ordering: lane stores -> __syncwarp (memory ordering among lanes) ->
//   lane0 arrive.release.cluster -> consumer try_wait acquire.cluster.
// ---------------------------------------------------------------------------
__global__ void __cluster_dims__(2, 1, 1) __launch_bounds__(256, 1)
mgu_scan(const float* __restrict__ Whw, const float* __restrict__ Whb,
         float* out)
{
    __shared__ __align__(16) float hsh[2 * PST];   // [p][b][half][HPITCH]
    __shared__ __align__(8)  ull  bars[2];

    const int tid = threadIdx.x;
    const int j   = tid >> 1;       // row within CTA half (0..127)
    const int kh  = tid & 1;        // K half (0..1)
    uint32_t rank;
    asm("mov.u32 %0, %%cluster_ctarank;" : "=r"(rank));
    const int jg = (int)rank * 128 + j;
    const int bbase = (blockIdx.x >> 1) * NB;
    const int b0 = 2 * kh;          // this lane finalizes batches b0, b0+1

    // --- W row half (128 floats) into 64 packed registers ---
    ull wv[64];
    {
        const ulonglong2* wp =
            (const ulonglong2*)(Whw + (size_t)jg * HH + kh * 128);
#pragma unroll
        for (int i = 0; i < 32; ++i) {
            ulonglong2 v = wp[i];
            wv[2 * i] = v.x; wv[2 * i + 1] = v.y;
        }
    }

    for (int i = tid; i < 2 * PST; i += 256) hsh[i] = 0.0f;

    if (tid == 0) {
        asm volatile("mbarrier.init.shared.b64 [%0], 16;"
                     :: "r"(smem_u32(&bars[0])) : "memory");
        asm volatile("mbarrier.init.shared.b64 [%0], 16;"
                     :: "r"(smem_u32(&bars[1])) : "memory");
    }

    const float biasr = Whb[jg];

    // out pointers for the 2 owned (batch,row) streams
    float* po0 = out + (size_t)(bbase + b0) * TT * HH + jg;
    float* po1 = po0 + (size_t)TT * HH;

    float gc0 = po0[0], gc1 = po1[0];   // gates t=0
    float hc0 = 0.0f, hc1 = 0.0f;       // persistent h for owned streams

    // cluster addresses
    const uint32_t hl  = smem_u32(hsh);
    const uint32_t bl0 = smem_u32(&bars[0]);
    uint32_t hr, br0;
    asm("mapa.shared::cluster.u32 %0, %1, %2;"
        : "=r"(hr) : "r"(hl), "r"(rank ^ 1u));
    asm("mapa.shared::cluster.u32 %0, %1, %2;"
        : "=r"(br0) : "r"(bl0), "r"(rank ^ 1u));

    // local/peer h store offsets (floats) within a buffer: [b][half=rank][j]
    const int st_off0 = b0 * BST + (int)rank * HPITCH + j;   // batch b0
    const int st_off1 = st_off0 + BST;                       // batch b0+1

    const bool lane0 = ((tid & 31) == 0);

    __syncthreads();
    // one-time: both CTAs' smem + mbarrier init visible cluster-wide
    asm volatile("barrier.cluster.arrive.aligned;" ::: "memory");
    asm volatile("barrier.cluster.wait.aligned;"   ::: "memory");

    uint32_t ph0 = 0, ph1 = 0;

#pragma unroll 1
    for (int t = 0; t < TT; ++t) {
        const int p = t & 1;
        const int q = p ^ 1;
        const bool not_last = (t + 1 < TT);

        // prefetch gates for t+1 (issued before the wait; DRAM hidden by step)
        float gn0 = 0.f, gn1 = 0.f;
        if (not_last) {
            const size_t o = (size_t)(t + 1) * HH;
            gn0 = po0[o]; gn1 = po1[o];
        }

        // step barrier: wait for all 16 warp-arrivals of step t-1 on mb[p]
        if (t > 0) {
            const uint32_t mb = bl0 + (uint32_t)p * 8u;
            const uint32_t par = p ? ph1 : ph0;
            uint32_t done;
            do {
                asm volatile(
                    "{\n\t.reg .pred P;\n\t"
                    "mbarrier.try_wait.parity.acquire.cluster.shared::cta.b64 "
                    "P, [%1], %2, 0x989680;\n\t"
                    "selp.b32 %0, 1, 0, P;\n\t}"
                    : "=r"(done) : "r"(mb), "r"(par) : "memory");
            } while (!done);
            if (p) ph1 ^= 1; else ph0 ^= 1;
        }

        // ---- matvec over this thread's K-half (128 elems = 32 x 4), 4 b ----
        const float* hb = hsh + p * PST + kh * HPITCH;
        const ulonglong2* x0 = (const ulonglong2*)(hb);
        const ulonglong2* x1 = (const ulonglong2*)(hb + BST);
        const ulonglong2* x2 = (const ulonglong2*)(hb + 2 * BST);
        const ulonglong2* x3 = (const ulonglong2*)(hb + 3 * BST);
        ull a0 = 0, a1 = 0, a2 = 0, a3 = 0;
#pragma unroll
        for (int i = 0; i < 32; ++i) {
            const ulonglong2 v0 = x0[i];
            const ulonglong2 v1 = x1[i];
            const ulonglong2 v2 = x2[i];
            const ulonglong2 v3 = x3[i];
            const ull wA = wv[2 * i], wB = wv[2 * i + 1];
            a0 = fma2(wA, v0.x, a0); a1 = fma2(wA, v1.x, a1);
            a2 = fma2(wA, v2.x, a2); a3 = fma2(wA, v3.x, a3);
            a0 = fma2(wB, v0.y, a0); a1 = fma2(wB, v1.y, a1);
            a2 = fma2(wB, v2.y, a2); a3 = fma2(wB, v3.y, a3);
        }
        // pair-sum within lane, then cross-lane pair reduce via shfl.xor(1)
        float2 u;
        u = unpack2(a0); float r0 = u.x + u.y;
        u = unpack2(a1); float r1 = u.x + u.y;
        u = unpack2(a2); float r2 = u.x + u.y;
        u = unpack2(a3); float r3 = u.x + u.y;
        const unsigned FULL = 0xffffffffu;
        const float s0 = r0 + __shfl_xor_sync(FULL, r0, 1);
        const float s1 = r1 + __shfl_xor_sync(FULL, r1, 1);
        const float s2 = r2 + __shfl_xor_sync(FULL, r2, 1);
        const float s3 = r3 + __shfl_xor_sync(FULL, r3, 1);

        // ---- update the 2 owned streams (h_prev in registers) ----
        const float zA = (kh ? s2 : s0) + biasr;
        const float zB = (kh ? s3 : s1) + biasr;
        const float thA = ftanh(zA);
        const float thB = ftanh(zB);
        hc0 = fmaf(gc0, hc0 - thA, thA);    // g*h + (1-g)*tanh
        hc1 = fmaf(gc1, hc1 - thB, thB);
        gc0 = gn0; gc1 = gn1;

        // ---- stores: out (always), local + peer h buffer q ----
        const size_t ot = (size_t)t * HH;
        po0[ot] = hc0;
        po1[ot] = hc1;
        if (not_last) {
            const int base = q * PST;
            hsh[base + st_off0] = hc0;
            hsh[base + st_off1] = hc1;
            const uint32_t ra0 = hr + (uint32_t)(base + st_off0) * 4u;
            const uint32_t ra1 = hr + (uint32_t)(base + st_off1) * 4u;
            asm volatile("st.shared::cluster.f32 [%0], %1;"
                         :: "r"(ra0), "f"(hc0) : "memory");
            asm volatile("st.shared::cluster.f32 [%0], %1;"
                         :: "r"(ra1), "f"(hc1) : "memory");
            // Warp-aggregated arrivals: syncwarp orders all lanes' stores,
            // then lane 0 arrives on local mb[q] and peer mb[q].
            __syncwarp();
            if (lane0) {
                const uint32_t off = (uint32_t)q * 8u;
                asm volatile(
                    "mbarrier.arrive.release.cluster.shared::cta.b64 _, [%0];"
                    :: "r"(bl0 + off) : "memory");
                asm volatile(
                    "mbarrier.arrive.release.cluster.shared::cluster.b64 _, [%0];"
                    :: "r"(br0 + off) : "memory");
            }
        }
    }

    // Trailing cluster sync: no CTA exits while peer DSMEM traffic may be
    // in flight toward it.
    asm volatile("barrier.cluster.arrive.aligned;" ::: "memory");
    asm volatile("barrier.cluster.wait.aligned;"   ::: "memory");
}

// ---------------------------------------------------------------------------
extern "C" void kernel_launch(void* const* d_in, const int* in_sizes, int n_in,
                              void* d_out, int out_size)
{
    const float* x   = (const float*)d_in[0];  // [B,T,E]
    const float* Wxw = (const float*)d_in[1];  // [H,E]
    const float* Wxb = (const float*)d_in[2];  // [H]
    const float* Whw = (const float*)d_in[3];  // [H,H]
    const float* Whb = (const float*)d_in[4];  // [H]
    float* out = (float*)d_out;                // [B,T,H]

    dim3 g1(BSZ * TT / 128, HH / 128);
    gates_kernel<<<g1, 256>>>(x, Wxw, Wxb, out);

    mgu_scan<<<(BSZ / NB) * 2, 256>>>(Whw, Whb, out);
}